// round 7
// baseline (speedup 1.0000x reference)
#include <cuda_runtime.h>
#include <cuda_fp16.h>
#include <cstdint>

#define BB 8
#define TT 512
#define SS 512
#define HH 128
#define TTILE 16
#define SCHUNK 64

// scratch (allocation-free rule: __device__ globals)
__device__ uint32_t g_WS2[BB*TT/2*HH];   // half2: (e^{-2ws}[t_even], e^{-2ws}[t_odd]) per h
__device__ uint32_t g_WH2[BB*SS*HH];     // half2: (e^{-2wh}, e^{-2wh}) duplicated
__device__ float    g_CT [BB*TT*HH];

__device__ __forceinline__ void cp16(uint32_t smem_dst, const void* gsrc){
    asm volatile("cp.async.ca.shared.global [%0], [%1], 16;" :: "r"(smem_dst), "l"(gsrc));
}
#define CP_COMMIT() asm volatile("cp.async.commit_group;")
template<int N> __device__ __forceinline__ void cp_wait(){
    asm volatile("cp.async.wait_group %0;" :: "n"(N));
}

// clamped exp(-2x): range keeps f16 normal, avoids 0*inf NaN
__device__ __forceinline__ float expm2_clamp(float x){
    float e = __expf(-2.f * x);
    return fminf(fmaxf(e, 6.2e-5f), 60000.f);
}

// ---------------------------------------------------------------------------
// K1: projections. grid (128, 2): y=0 -> exp(-2*q.Ws) -> g_WS2 (t-paired h2),
//                                 y=1 -> exp(-2*enc.Wh) -> g_WH2 (dup h2).
// 32 rows/block; thread = 4 rows x 4 cols; h vectorized by float4.
// ---------------------------------------------------------------------------
__global__ __launch_bounds__(256) void k_proj(
    const float* __restrict__ q, const float* __restrict__ enc,
    const float* __restrict__ Ws, const float* __restrict__ Wh)
{
    extern __shared__ float sm[];
    float* insm = sm;            // 32 x 128
    float* Wsm  = sm + 32*128;   // 128 cols x 36 (stride 36: LDS.128 conflict-free)

    const float* in; const float* W;
    if (blockIdx.y == 0) { in = q;   W = Ws; }
    else                 { in = enc; W = Wh; }
    int tid = threadIdx.x;
    int i0 = blockIdx.x * 32;    // global row (over b*T or b*S)

    {   // stage input rows (float4, coalesced)
        const float4* inv = (const float4*)(in + i0*128);
        float4* insv = (float4*)insm;
        #pragma unroll
        for (int k = 0; k < 4; k++) insv[tid + 256*k] = inv[tid + 256*k];
    }

    int cg = tid & 31;          // cols = cg + 32*j
    int rg = tid >> 5;          // rows = rg*4 + r (warp-uniform)
    float acc[4][4];
    #pragma unroll
    for (int r = 0; r < 4; r++)
        #pragma unroll
        for (int j = 0; j < 4; j++) acc[r][j] = 0.f;

    #pragma unroll 1
    for (int hc = 0; hc < 4; hc++) {          // 32-h chunks
        __syncthreads();
        #pragma unroll
        for (int k = 0; k < 4; k++) {         // stage W chunk: 128 cols x 32 h = 1024 float4
            int idx = tid + 256*k;
            int col = idx >> 3, kk = idx & 7;
            float4 w = *(const float4*)(W + col*128 + hc*32 + kk*4);
            *(float4*)(Wsm + col*36 + kk*4) = w;
        }
        __syncthreads();
        #pragma unroll
        for (int k8 = 0; k8 < 8; k8++) {
            float4 cv[4];
            #pragma unroll
            for (int j = 0; j < 4; j++)
                cv[j] = *(const float4*)(Wsm + (cg + 32*j)*36 + k8*4);
            float4 rv[4];
            #pragma unroll
            for (int r = 0; r < 4; r++)
                rv[r] = *(const float4*)(insm + (rg*4 + r)*128 + hc*32 + k8*4);
            #pragma unroll
            for (int r = 0; r < 4; r++)
                #pragma unroll
                for (int j = 0; j < 4; j++) {
                    acc[r][j] += rv[r].x*cv[j].x;
                    acc[r][j] += rv[r].y*cv[j].y;
                    acc[r][j] += rv[r].z*cv[j].z;
                    acc[r][j] += rv[r].w*cv[j].w;
                }
        }
    }
    if (blockIdx.y == 0) {
        // pack t-pairs: rows (rg*4+0, +1) and (+2, +3); store exp(-2*ws)
        #pragma unroll
        for (int r = 0; r < 4; r += 2)
            #pragma unroll
            for (int j = 0; j < 4; j++) {
                __half2 p = __floats2half2_rn(expm2_clamp(acc[r][j]),
                                              expm2_clamp(acc[r+1][j]));  // x=even t
                int pair = (i0 + rg*4 + r) >> 1;
                g_WS2[pair*128 + cg + 32*j] = *(uint32_t*)&p;
            }
    } else {
        #pragma unroll
        for (int r = 0; r < 4; r++)
            #pragma unroll
            for (int j = 0; j < 4; j++) {
                float e = expm2_clamp(acc[r][j]);
                __half2 d = __floats2half2_rn(e, e);
                g_WH2[(i0 + rg*4 + r)*128 + cg + 32*j] = *(uint32_t*)&d;
            }
    }
}

// ---------------------------------------------------------------------------
// K2: fused scores (exp/rcp identity) + masked softmax + ct.
// tanh(ws+wh) = 2/(1 + e^{-2ws} e^{-2wh}) - 1
// score = 2*sum_h v_h * r_h - sum_h v_h
// grid 256 = (b, t-tile of 16), 256 threads, occ 2.
// ---------------------------------------------------------------------------
#define NB_U32   (SCHUNK*132)                 // one staging buffer, u32 units
#define OFF_BUF0 0
#define OFF_BUF1 (NB_U32)
#define OFF_SC   (2*NB_U32)                   // scores: 16*512 floats
#define OFF_WS2  (OFF_SC + TTILE*512)         // 8 t-pairs x 128 h (u32)
#define OFF_V    (OFF_WS2 + 8*128)            // 128 u32 (dup half2 of v)
#define OFF_INV  (OFF_V + 128)                // 16 floats
#define OFF_SUMV (OFF_INV + 16)               // 1 float
#define SM2_U32  (OFF_SUMV + 4)

__global__ __launch_bounds__(256, 2) void k_attn(
    const float* __restrict__ enc, const int* __restrict__ lens,
    const float* __restrict__ vvec)
{
    extern __shared__ uint32_t smu[];
    float*    scores = (float*)(smu + OFF_SC);
    uint32_t* wsh2   = smu + OFF_WS2;
    uint32_t* vsm2   = smu + OFF_V;
    float*    invsum = (float*)(smu + OFF_INV);
    float*    sumvp  = (float*)(smu + OFF_SUMV);
    uint32_t  smbase = (uint32_t)__cvta_generic_to_shared(smu);

    int tid = threadIdx.x;
    int b  = blockIdx.x >> 5;
    int t0 = (blockIdx.x & 31) * TTILE;
    int len = __ldg(&lens[b]);
    int warp = tid >> 5, lane = tid & 31;

    // prefetch WH2 chunk 0 into buf0 (16B cp.async, s-major rows w/ pad 132)
    {
        const uint32_t* src0 = g_WH2 + (b*SS)*128;
        #pragma unroll
        for (int k = 0; k < 8; k++) {
            int idx = tid + 256*k;            // 2048 x 16B
            int ss = idx >> 5, kk = idx & 31;
            cp16(smbase + (OFF_BUF0 + ss*132 + kk*4)*4, src0 + ss*128 + kk*4);
        }
        CP_COMMIT();
    }

    // stage ws pairs + v (dup half2) + sumv
    {
        const uint32_t* wsrc = g_WS2 + (b*256 + t0/2)*128;
        #pragma unroll
        for (int k = 0; k < 4; k++) wsh2[tid + 256*k] = wsrc[tid + 256*k];
        if (tid < 128) {
            float vv = vvec[tid];
            __half2 d = __floats2half2_rn(vv, vv);
            vsm2[tid] = *(uint32_t*)&d;
        }
        if (warp == 0) {
            float sv = vvec[lane] + vvec[lane+32] + vvec[lane+64] + vvec[lane+96];
            #pragma unroll
            for (int o = 16; o > 0; o >>= 1) sv += __shfl_xor_sync(0xffffffffu, sv, o);
            if (lane == 0) *sumvp = sv;
        }
    }

    // ---- Phase B: scores. warp = (t-quad tq, s-half sh). HMUL2/HADD2/h2rcp/HFMA2. ----
    int tq = warp >> 1, sh = warp & 1;
    int s  = sh*32 + lane;
    const uint32_t* wsA = wsh2 + (tq*2 + 0)*128;   // (t=4tq+0, 4tq+1)
    const uint32_t* wsB = wsh2 + (tq*2 + 1)*128;   // (t=4tq+2, 4tq+3)
    const __half2 one2 = __floats2half2_rn(1.f, 1.f);

    for (int c = 0; c < 8; c++) {
        // prefetch next chunk (or enc chunk 0 for phase D on the last iter)
        if (c + 1 < 8) {
            const uint32_t* src = g_WH2 + (b*SS + (c+1)*SCHUNK)*128;
            uint32_t dstoff = ((c+1) & 1) ? OFF_BUF1 : OFF_BUF0;
            #pragma unroll
            for (int k = 0; k < 8; k++) {
                int idx = tid + 256*k;
                int ss = idx >> 5, kk = idx & 31;
                cp16(smbase + (dstoff + ss*132 + kk*4)*4, src + ss*128 + kk*4);
            }
        } else {
            const float* src = enc + (b*SS)*128;
            #pragma unroll
            for (int k = 0; k < 8; k++) {
                int idx = tid + 256*k;
                int ss = idx >> 5, kk = idx & 31;
                cp16(smbase + (OFF_BUF0 + ss*128 + kk*4)*4, src + ss*128 + kk*4);
            }
        }
        CP_COMMIT();
        cp_wait<1>();
        __syncthreads();

        const uint32_t* whrow = smu + ((c & 1) ? OFF_BUF1 : OFF_BUF0) + s*132;
        float a0 = 0.f, a1 = 0.f, a2 = 0.f, a3 = 0.f;
        #pragma unroll
        for (int hb = 0; hb < 128; hb += 8) {      // flush f16 accumulators every 8 h
            __half2 accA = __float2half2_rn(0.f);
            __half2 accB = __float2half2_rn(0.f);
            #pragma unroll
            for (int g = 0; g < 8; g += 4) {
                uint4 wh4 = *(const uint4*)(whrow + hb + g);
                uint4 wA4 = *(const uint4*)(wsA + hb + g);
                uint4 wB4 = *(const uint4*)(wsB + hb + g);
                uint4 vv4 = *(const uint4*)(vsm2 + hb + g);
                #define STEP(WH, WA, WB, VV)                                     \
                {                                                                \
                    __half2 hw = *(__half2*)&(WH);                               \
                    __half2 wa = __hmul2(hw, *(__half2*)&(WA));                  \
                    __half2 wb = __hmul2(hw, *(__half2*)&(WB));                  \
                    __half2 da = __hadd2(one2, wa);                              \
                    __half2 db = __hadd2(one2, wb);                              \
                    __half2 ra = h2rcp(da);                                      \
                    __half2 rb = h2rcp(db);                                      \
                    __half2 v2 = *(__half2*)&(VV);                               \
                    accA = __hfma2(v2, ra, accA);                                \
                    accB = __hfma2(v2, rb, accB);                                \
                }
                STEP(wh4.x, wA4.x, wB4.x, vv4.x)
                STEP(wh4.y, wA4.y, wB4.y, vv4.y)
                STEP(wh4.z, wA4.z, wB4.z, vv4.z)
                STEP(wh4.w, wA4.w, wB4.w, vv4.w)
                #undef STEP
            }
            float2 fA = __half22float2(accA);
            float2 fB = __half22float2(accB);
            a0 = fmaf(2.f, fA.x, a0); a1 = fmaf(2.f, fA.y, a1);
            a2 = fmaf(2.f, fB.x, a2); a3 = fmaf(2.f, fB.y, a3);
        }
        float sumv = *sumvp;
        int sg = c*SCHUNK + s;
        float m = (sg < len) ? 1.f : 0.f;     // reference quirk: zero, not -inf
        scores[(tq*4 + 0)*512 + sg] = (a0 - sumv) * m;
        scores[(tq*4 + 1)*512 + sg] = (a1 - sumv) * m;
        scores[(tq*4 + 2)*512 + sg] = (a2 - sumv) * m;
        scores[(tq*4 + 3)*512 + sg] = (a3 - sumv) * m;
        __syncthreads();
    }

    // ---- Phase C: softmax over full 512 (zeros included) ----
    #pragma unroll
    for (int it = 0; it < 2; it++) {
        int t = warp + 8*it;
        float* row = scores + t*512;
        float loc[16];
        float mx = -1e30f;
        #pragma unroll
        for (int k = 0; k < 16; k++) { loc[k] = row[lane + 32*k]; mx = fmaxf(mx, loc[k]); }
        #pragma unroll
        for (int o = 16; o > 0; o >>= 1) mx = fmaxf(mx, __shfl_xor_sync(0xffffffffu, mx, o));
        float sum = 0.f;
        #pragma unroll
        for (int k = 0; k < 16; k++) {
            float p = __expf(loc[k] - mx);
            row[lane + 32*k] = p;
            sum += p;
        }
        #pragma unroll
        for (int o = 16; o > 0; o >>= 1) sum += __shfl_xor_sync(0xffffffffu, sum, o);
        if (lane == 0) invsum[t] = 1.f / sum;
    }

    // ---- Phase D: ct[t,h] = (1/sum) * sum_s p[t,s] * enc[s,h] ----
    int tp = tid >> 5;            // t-pair 0..7
    int h0 = (tid & 31) * 4;      // 4 h per thread
    int tA = tp*2, tB = tA + 1;
    float a0x=0,a0y=0,a0z=0,a0w=0, a1x=0,a1y=0,a1z=0,a1w=0;
    for (int d = 0; d < 8; d++) {
        if (d + 1 < 8) {
            const float* src = enc + (b*SS + (d+1)*SCHUNK)*128;
            uint32_t dstoff = ((d+1) & 1) ? OFF_BUF1 : OFF_BUF0;
            #pragma unroll
            for (int k = 0; k < 8; k++) {
                int idx = tid + 256*k;
                int ss = idx >> 5, kk = idx & 31;
                cp16(smbase + (dstoff + ss*128 + kk*4)*4, src + ss*128 + kk*4);
            }
            CP_COMMIT();
            cp_wait<1>();
        } else {
            cp_wait<0>();
        }
        __syncthreads();
        const float* encsm = (const float*)(smu + ((d & 1) ? OFF_BUF1 : OFF_BUF0));
        #pragma unroll 4
        for (int ss = 0; ss < SCHUNK; ss++) {
            float4 e = *(const float4*)(encsm + ss*128 + h0);
            float p0 = scores[tA*512 + d*SCHUNK + ss];   // broadcast
            float p1 = scores[tB*512 + d*SCHUNK + ss];
            a0x += p0*e.x; a0y += p0*e.y; a0z += p0*e.z; a0w += p0*e.w;
            a1x += p1*e.x; a1y += p1*e.y; a1z += p1*e.z; a1w += p1*e.w;
        }
        __syncthreads();
    }
    float i0 = invsum[tA], i1 = invsum[tB];
    float4 r0 = make_float4(a0x*i0, a0y*i0, a0z*i0, a0w*i0);
    float4 r1 = make_float4(a1x*i1, a1y*i1, a1z*i1, a1w*i1);
    *(float4*)(g_CT + (b*TT + t0 + tA)*128 + h0) = r0;
    *(float4*)(g_CT + (b*TT + t0 + tB)*128 + h0) = r1;
}

// ---------------------------------------------------------------------------
// K3: out[t,o] = tanh( sum_c W[o,c]*concat[t,c] + bias[o] )
// grid 256 = (b, t-tile of 16); thread = 4t x 2o; c vectorized by float4.
// ---------------------------------------------------------------------------
__global__ __launch_bounds__(256, 2) void k_out(
    const float* __restrict__ q, const float* __restrict__ Wout,
    const float* __restrict__ bias, float* __restrict__ out)
{
    extern __shared__ float sm[];
    float* concat = sm;               // 16 x 256
    float* Wsm    = concat + 16*256;  // 128 x 132 (c-chunk, LDS.128-friendly pad)
    float* bsm    = Wsm + 128*132;    // 128

    int tid = threadIdx.x;
    int b  = blockIdx.x >> 5;
    int t0 = (blockIdx.x & 31) * 16;

    {   // stage concat (float4)
        #pragma unroll
        for (int k = 0; k < 4; k++) {
            int idx = tid + 256*k;          // 1024 float4
            int t = idx >> 6, c4 = idx & 63;
            float4 v;
            if (c4 < 32) v = *(const float4*)(g_CT + (b*TT + t0 + t)*128 + c4*4);
            else         v = *(const float4*)(q    + (b*TT + t0 + t)*128 + (c4-32)*4);
            *(float4*)(concat + t*256 + c4*4) = v;
        }
    }
    if (tid < 128) bsm[tid] = bias[tid];

    int og = tid & 63;          // o = og, og + 64
    int tg = tid >> 6;          // 4 t-groups x 4 t; warp-uniform
    float acc[4][2];
    #pragma unroll
    for (int k = 0; k < 4; k++) { acc[k][0] = 0.f; acc[k][1] = 0.f; }

    for (int c0 = 0; c0 < 256; c0 += 128) {
        __syncthreads();
        // staging: chunk is 128 o x 128 c = 4096 float4 (16 iters x 256 thr)
        #pragma unroll
        for (int k = 0; k < 16; k++) {
            int idx = tid + 256*k;
            int o = idx >> 5, kk = idx & 31;      // kk*4 covers c 0..127
            float4 w = *(const float4*)(Wout + o*256 + c0 + kk*4);
            *(float4*)(Wsm + o*132 + kk*4) = w;
        }
        __syncthreads();
        #pragma unroll 4
        for (int cl = 0; cl < 128; cl += 4) {
            float4 w0 = *(const float4*)(Wsm + og*132 + cl);
            float4 w1 = *(const float4*)(Wsm + (og + 64)*132 + cl);
            #pragma unroll
            for (int k = 0; k < 4; k++) {
                float4 cc = *(const float4*)(concat + (tg*4 + k)*256 + c0 + cl);
                acc[k][0] += w0.x*cc.x + w0.y*cc.y + w0.z*cc.z + w0.w*cc.w;
                acc[k][1] += w1.x*cc.x + w1.y*cc.y + w1.z*cc.z + w1.w*cc.w;
            }
        }
    }
    #pragma unroll
    for (int k = 0; k < 4; k++) {
        int t = t0 + tg*4 + k;
        out[(b*TT + t)*128 + og     ] = tanhf(acc[k][0] + bsm[og]);
        out[(b*TT + t)*128 + og + 64] = tanhf(acc[k][1] + bsm[og + 64]);
    }
}

// ---------------------------------------------------------------------------
extern "C" void kernel_launch(void* const* d_in, const int* in_sizes, int n_in,
                              void* d_out, int out_size)
{
    (void)in_sizes; (void)n_in; (void)out_size;
    const float* q    = (const float*)d_in[0];
    const float* enc  = (const float*)d_in[1];
    const int*   lens = (const int*)  d_in[2];
    const float* Wh   = (const float*)d_in[3];
    const float* Ws   = (const float*)d_in[4];
    const float* v    = (const float*)d_in[5];
    const float* Wout = (const float*)d_in[6];
    const float* bias = (const float*)d_in[7];
    float* out = (float*)d_out;

    int sm1 = (32*128 + 128*36) * 4;     // 34816 B
    int sm2 = SM2_U32 * 4;               // ~105 KB
    int sm3 = (16*256 + 128*132 + 128) * 4;
    cudaFuncSetAttribute(k_proj, cudaFuncAttributeMaxDynamicSharedMemorySize, sm1);
    cudaFuncSetAttribute(k_attn, cudaFuncAttributeMaxDynamicSharedMemorySize, sm2);
    cudaFuncSetAttribute(k_out,  cudaFuncAttributeMaxDynamicSharedMemorySize, sm3);

    dim3 g1(128, 2);
    k_proj<<<g1, 256, sm1>>>(q, enc, Ws, Wh);
    k_attn<<<256, 256, sm2>>>(enc, lens, v);
    k_out <<<256, 256, sm3>>>(q, Wout, bias, out);
}

// round 8
// speedup vs baseline: 1.2801x; 1.2801x over previous
#include <cuda_runtime.h>
#include <cuda_fp16.h>
#include <cstdint>

#define BB 8
#define TT 512
#define SS 512
#define HH 128

// scratch (allocation-free rule: __device__ globals)
__device__ uint32_t g_WS2[BB*TT/2*HH];   // half2: (WS[t_even], WS[t_odd]) per h
__device__ uint32_t g_WH2[BB*SS*HH];     // half2: (WH, WH) duplicated
__device__ uint32_t g_V2 [HH];           // half2: (v, v) duplicated
__device__ float    g_SC [BB*TT*SS];     // raw masked scores (8 MB, L2-resident)
__device__ float    g_CT [BB*TT*HH];

__device__ __forceinline__ uint32_t tanh2_u(uint32_t a){
    uint32_t r; asm("tanh.approx.f16x2 %0, %1;" : "=r"(r) : "r"(a)); return r;
}
__device__ __forceinline__ void cp16(uint32_t smem_dst, const void* gsrc){
    asm volatile("cp.async.ca.shared.global [%0], [%1], 16;" :: "r"(smem_dst), "l"(gsrc));
}
#define CP_COMMIT() asm volatile("cp.async.commit_group;")
template<int N> __device__ __forceinline__ void cp_wait(){
    asm volatile("cp.async.wait_group %0;" :: "n"(N));
}

// ---------------------------------------------------------------------------
// K0: pack v into dup-half2
// ---------------------------------------------------------------------------
__global__ void k_packv(const float* __restrict__ vvec){
    int i = threadIdx.x;
    __half2 d = __half2half2(__float2half_rn(vvec[i]));
    g_V2[i] = *(uint32_t*)&d;
}

// ---------------------------------------------------------------------------
// K1: projections. grid (128, 2): y=0 -> WS(query,W_s) -> g_WS2 (t-paired h2),
//                                 y=1 -> WH(enc,W_h)   -> g_WH2 (dup h2).
// ---------------------------------------------------------------------------
__global__ __launch_bounds__(256) void k_proj(
    const float* __restrict__ q, const float* __restrict__ enc,
    const float* __restrict__ Ws, const float* __restrict__ Wh)
{
    extern __shared__ float sm[];
    float* insm = sm;            // 32 x 128
    float* Wsm  = sm + 32*128;   // 128 cols x 36

    const float* in; const float* W;
    if (blockIdx.y == 0) { in = q;   W = Ws; }
    else                 { in = enc; W = Wh; }
    int tid = threadIdx.x;
    int i0 = blockIdx.x * 32;

    {
        const float4* inv = (const float4*)(in + i0*128);
        float4* insv = (float4*)insm;
        #pragma unroll
        for (int k = 0; k < 4; k++) insv[tid + 256*k] = inv[tid + 256*k];
    }

    int cg = tid & 31;
    int rg = tid >> 5;
    float acc[4][4];
    #pragma unroll
    for (int r = 0; r < 4; r++)
        #pragma unroll
        for (int j = 0; j < 4; j++) acc[r][j] = 0.f;

    #pragma unroll 1
    for (int hc = 0; hc < 4; hc++) {
        __syncthreads();
        #pragma unroll
        for (int k = 0; k < 4; k++) {
            int idx = tid + 256*k;
            int col = idx >> 3, kk = idx & 7;
            float4 w = *(const float4*)(W + col*128 + hc*32 + kk*4);
            *(float4*)(Wsm + col*36 + kk*4) = w;
        }
        __syncthreads();
        #pragma unroll
        for (int k8 = 0; k8 < 8; k8++) {
            float4 cv[4];
            #pragma unroll
            for (int j = 0; j < 4; j++)
                cv[j] = *(const float4*)(Wsm + (cg + 32*j)*36 + k8*4);
            float4 rv[4];
            #pragma unroll
            for (int r = 0; r < 4; r++)
                rv[r] = *(const float4*)(insm + (rg*4 + r)*128 + hc*32 + k8*4);
            #pragma unroll
            for (int r = 0; r < 4; r++)
                #pragma unroll
                for (int j = 0; j < 4; j++) {
                    acc[r][j] += rv[r].x*cv[j].x;
                    acc[r][j] += rv[r].y*cv[j].y;
                    acc[r][j] += rv[r].z*cv[j].z;
                    acc[r][j] += rv[r].w*cv[j].w;
                }
        }
    }
    if (blockIdx.y == 0) {
        #pragma unroll
        for (int r = 0; r < 4; r += 2)
            #pragma unroll
            for (int j = 0; j < 4; j++) {
                __half2 p = __floats2half2_rn(acc[r][j], acc[r+1][j]);  // x=even t
                int pair = (i0 + rg*4 + r) >> 1;
                g_WS2[pair*128 + cg + 32*j] = *(uint32_t*)&p;
            }
    } else {
        #pragma unroll
        for (int r = 0; r < 4; r++)
            #pragma unroll
            for (int j = 0; j < 4; j++) {
                __half2 d = __half2half2(__float2half_rn(acc[r][j]));
                g_WH2[(i0 + rg*4 + r)*128 + cg + 32*j] = *(uint32_t*)&d;
            }
    }
}

// ---------------------------------------------------------------------------
// K2: scores only. grid 2048 = (b, t-tile of 16, s-chunk of 64).
// Early-exit (write zeros) when whole s-chunk masked.
// ---------------------------------------------------------------------------
__global__ __launch_bounds__(256) void k_scores(
    const int* __restrict__ lens)
{
    __shared__ uint32_t s_wh[64*132];   // transposed s-chunk, pad 132
    __shared__ uint32_t s_ws[8*128];    // 8 t-pairs x 128 h
    __shared__ uint32_t s_v [128];      // dup half2 of v

    int bx = blockIdx.x;
    int b  = bx >> 8;
    int tt = (bx >> 3) & 31;
    int sc = bx & 7;
    int t0 = tt*16, s0 = sc*64;
    int tid = threadIdx.x;
    int len = __ldg(&lens[b]);

    if (s0 >= len) {   // fully masked: write zeros (reference quirk)
        int r = tid >> 4, c4 = tid & 15;
        *(float4*)(g_SC + (b*TT + t0 + r)*SS + s0 + c4*4) = make_float4(0.f,0.f,0.f,0.f);
        return;
    }

    uint32_t smbase = (uint32_t)__cvta_generic_to_shared(s_wh);
    {   // stage WH chunk (transposed, cp.async)
        const uint32_t* src = g_WH2 + (b*SS + s0)*128;
        #pragma unroll
        for (int k = 0; k < 8; k++) {
            int idx = tid + 256*k;            // 2048 x 16B
            int ss = idx >> 5, kk = idx & 31;
            cp16(smbase + (ss*132 + kk*4)*4, src + ss*128 + kk*4);
        }
        CP_COMMIT();
    }
    {   // stage ws pairs + v
        const uint32_t* wsrc = g_WS2 + (b*(TT/2) + t0/2)*128;
        #pragma unroll
        for (int k = 0; k < 4; k++) s_ws[tid + 256*k] = wsrc[tid + 256*k];
        if (tid < 128) s_v[tid] = g_V2[tid];
    }
    cp_wait<0>();
    __syncthreads();

    int warp = tid >> 5, lane = tid & 31;
    int tq = warp >> 1, sh = warp & 1;
    int s  = sh*32 + lane;
    const uint32_t* wsA = s_ws + (tq*2 + 0)*128;   // (t=4tq+0, 4tq+1)
    const uint32_t* wsB = s_ws + (tq*2 + 1)*128;   // (t=4tq+2, 4tq+3)
    const uint32_t* whrow = s_wh + s*132;

    float a0 = 0.f, a1 = 0.f, a2 = 0.f, a3 = 0.f;
    #pragma unroll
    for (int hb = 0; hb < 128; hb += 8) {      // flush f16 accumulators every 8 h
        __half2 accA = __float2half2_rn(0.f);
        __half2 accB = __float2half2_rn(0.f);
        #pragma unroll
        for (int g = 0; g < 8; g += 4) {
            uint4 wh4 = *(const uint4*)(whrow + hb + g);
            uint4 wA4 = *(const uint4*)(wsA + hb + g);
            uint4 wB4 = *(const uint4*)(wsB + hb + g);
            uint4 vv4 = *(const uint4*)(s_v + hb + g);
            #define STEP(WH, WA, WB, VV)                                     \
            {                                                                \
                __half2 hw = *(__half2*)&(WH);                               \
                __half2 aA = __hadd2(hw, *(__half2*)&(WA));                  \
                __half2 aB = __hadd2(hw, *(__half2*)&(WB));                  \
                uint32_t tA = tanh2_u(*(uint32_t*)&aA);                      \
                uint32_t tB = tanh2_u(*(uint32_t*)&aB);                      \
                __half2 v2 = *(__half2*)&(VV);                               \
                accA = __hfma2(v2, *(__half2*)&tA, accA);                    \
                accB = __hfma2(v2, *(__half2*)&tB, accB);                    \
            }
            STEP(wh4.x, wA4.x, wB4.x, vv4.x)
            STEP(wh4.y, wA4.y, wB4.y, vv4.y)
            STEP(wh4.z, wA4.z, wB4.z, vv4.z)
            STEP(wh4.w, wA4.w, wB4.w, vv4.w)
            #undef STEP
        }
        float2 fA = __half22float2(accA);
        float2 fB = __half22float2(accB);
        a0 += fA.x; a1 += fA.y;
        a2 += fB.x; a3 += fB.y;
    }
    int sg = s0 + s;
    float m = (sg < len) ? 1.f : 0.f;          // reference quirk: zero, not -inf
    g_SC[(b*TT + t0 + tq*4 + 0)*SS + sg] = a0 * m;
    g_SC[(b*TT + t0 + tq*4 + 1)*SS + sg] = a1 * m;
    g_SC[(b*TT + t0 + tq*4 + 2)*SS + sg] = a2 * m;
    g_SC[(b*TT + t0 + tq*4 + 3)*SS + sg] = a3 * m;
}

// ---------------------------------------------------------------------------
// K3: softmax + ct. grid 256 = (b, t-tile of 16), 256 threads.
// Phase D: direct coalesced LDG of enc, thread = 4t x 4h, s-split + reduce.
// ---------------------------------------------------------------------------
__global__ __launch_bounds__(256) void k_smct(
    const float* __restrict__ enc)
{
    __shared__ float scores[16*512];
    __shared__ float invsum[16];

    int tid = threadIdx.x;
    int b  = blockIdx.x >> 5;
    int t0 = (blockIdx.x & 31) * 16;
    int warp = tid >> 5, lane = tid & 31;

    {   // stage scores (cp.async, 32 KB, coalesced)
        uint32_t smbase = (uint32_t)__cvta_generic_to_shared(scores);
        const float* src = g_SC + (b*TT + t0)*SS;
        #pragma unroll
        for (int k = 0; k < 8; k++) {
            int idx = tid + 256*k;            // 2048 x 16B
            cp16(smbase + idx*16, src + idx*4);
        }
        CP_COMMIT();
        cp_wait<0>();
        __syncthreads();
    }

    // ---- softmax over full 512 (zeros included) ----
    #pragma unroll
    for (int it = 0; it < 2; it++) {
        int t = warp + 8*it;
        float* row = scores + t*512;
        float loc[16];
        float mx = -1e30f;
        #pragma unroll
        for (int k = 0; k < 16; k++) { loc[k] = row[lane + 32*k]; mx = fmaxf(mx, loc[k]); }
        #pragma unroll
        for (int o = 16; o > 0; o >>= 1) mx = fmaxf(mx, __shfl_xor_sync(0xffffffffu, mx, o));
        float sum = 0.f;
        #pragma unroll
        for (int k = 0; k < 16; k++) {
            float p = __expf(loc[k] - mx);
            row[lane + 32*k] = p;
            sum += p;
        }
        #pragma unroll
        for (int o = 16; o > 0; o >>= 1) sum += __shfl_xor_sync(0xffffffffu, sum, o);
        if (lane == 0) invsum[t] = 1.f / sum;
    }
    __syncthreads();

    // ---- ct ----
    int sw = warp >> 2;          // s half
    int tg = warp & 3;           // t group of 4
    int h0 = lane * 4;
    float4 acc[4];
    #pragma unroll
    for (int t = 0; t < 4; t++) acc[t] = make_float4(0.f,0.f,0.f,0.f);

    const float* eb = enc + (b*SS + sw*256)*128;
    const float* prow = scores + (tg*4)*512 + sw*256;
    #pragma unroll 4
    for (int s = 0; s < 256; s++) {
        float4 e = __ldg((const float4*)(eb + s*128 + h0));
        #pragma unroll
        for (int t = 0; t < 4; t++) {
            float p = prow[t*512 + s];
            acc[t].x += p*e.x; acc[t].y += p*e.y;
            acc[t].z += p*e.z; acc[t].w += p*e.w;
        }
    }
    __syncthreads();
    float* red = scores;                     // reuse as reduction buffer
    if (sw == 1) {
        float* dst = red + (tg*32 + lane)*16;
        #pragma unroll
        for (int t = 0; t < 4; t++) *(float4*)(dst + t*4) = acc[t];
    }
    __syncthreads();
    if (sw == 0) {
        const float* srcr = red + (tg*32 + lane)*16;
        #pragma unroll
        for (int t = 0; t < 4; t++) {
            float4 o = *(const float4*)(srcr + t*4);
            float iv = invsum[tg*4 + t];
            o.x = (acc[t].x + o.x)*iv; o.y = (acc[t].y + o.y)*iv;
            o.z = (acc[t].z + o.z)*iv; o.w = (acc[t].w + o.w)*iv;
            *(float4*)(g_CT + (b*TT + t0 + tg*4 + t)*128 + h0) = o;
        }
    }
}

// ---------------------------------------------------------------------------
// K4: out = tanh(W_out . concat + b). grid 256; 128 threads; thread = 4t x 4o.
// ---------------------------------------------------------------------------
__global__ __launch_bounds__(128, 2) void k_out(
    const float* __restrict__ q, const float* __restrict__ Wout,
    const float* __restrict__ bias, float* __restrict__ out)
{
    extern __shared__ float sm[];
    float* concat = sm;               // 16 x 256
    float* Wsm    = concat + 16*256;  // 128 x 132
    float* bsm    = Wsm + 128*132;    // 128

    int tid = threadIdx.x;
    int b  = blockIdx.x >> 5;
    int t0 = (blockIdx.x & 31) * 16;

    {
        #pragma unroll
        for (int k = 0; k < 8; k++) {
            int idx = tid + 128*k;          // 1024 float4
            int t = idx >> 6, c4 = idx & 63;
            float4 v;
            if (c4 < 32) v = *(const float4*)(g_CT + (b*TT + t0 + t)*128 + c4*4);
            else         v = *(const float4*)(q    + (b*TT + t0 + t)*128 + (c4-32)*4);
            *(float4*)(concat + t*256 + c4*4) = v;
        }
    }
    bsm[tid] = bias[tid];

    int og = tid & 31;          // o = og + 32*j
    int tg = tid >> 5;          // 4 t-groups of 4 t
    float acc[4][4];
    #pragma unroll
    for (int t = 0; t < 4; t++)
        #pragma unroll
        for (int j = 0; j < 4; j++) acc[t][j] = 0.f;

    for (int c0 = 0; c0 < 256; c0 += 128) {
        __syncthreads();
        #pragma unroll
        for (int k = 0; k < 32; k++) {        // 4096 float4
            int idx = tid + 128*k;
            int o = idx >> 5, kk = idx & 31;
            float4 w = *(const float4*)(Wout + o*256 + c0 + kk*4);
            *(float4*)(Wsm + o*132 + kk*4) = w;
        }
        __syncthreads();
        #pragma unroll 4
        for (int cl = 0; cl < 128; cl += 4) {
            float4 w[4];
            #pragma unroll
            for (int j = 0; j < 4; j++)
                w[j] = *(const float4*)(Wsm + (og + 32*j)*132 + cl);
            #pragma unroll
            for (int t = 0; t < 4; t++) {
                float4 cc = *(const float4*)(concat + (tg*4 + t)*256 + c0 + cl);
                #pragma unroll
                for (int j = 0; j < 4; j++)
                    acc[t][j] += w[j].x*cc.x + w[j].y*cc.y + w[j].z*cc.z + w[j].w*cc.w;
            }
        }
    }
    #pragma unroll
    for (int t = 0; t < 4; t++) {
        int tt = t0 + tg*4 + t;
        #pragma unroll
        for (int j = 0; j < 4; j++)
            out[(b*TT + tt)*128 + og + 32*j] = tanhf(acc[t][j] + bsm[og + 32*j]);
    }
}

// ---------------------------------------------------------------------------
extern "C" void kernel_launch(void* const* d_in, const int* in_sizes, int n_in,
                              void* d_out, int out_size)
{
    (void)in_sizes; (void)n_in; (void)out_size;
    const float* q    = (const float*)d_in[0];
    const float* enc  = (const float*)d_in[1];
    const int*   lens = (const int*)  d_in[2];
    const float* Wh   = (const float*)d_in[3];
    const float* Ws   = (const float*)d_in[4];
    const float* v    = (const float*)d_in[5];
    const float* Wout = (const float*)d_in[6];
    const float* bias = (const float*)d_in[7];
    float* out = (float*)d_out;

    int sm1 = (32*128 + 128*36) * 4;            // 34816 B
    int sm4 = (16*256 + 128*132 + 128) * 4;     // 84480 B
    cudaFuncSetAttribute(k_proj, cudaFuncAttributeMaxDynamicSharedMemorySize, sm1);
    cudaFuncSetAttribute(k_out,  cudaFuncAttributeMaxDynamicSharedMemorySize, sm4);

    dim3 g1(128, 2);
    k_packv<<<1, 128>>>(v);
    k_proj<<<g1, 256, sm1>>>(q, enc, Ws, Wh);
    k_scores<<<2048, 256>>>(lens);
    k_smct<<<256, 256>>>(enc);
    k_out<<<256, 128, sm4>>>(q, Wout, bias, out);
}

// round 9
// speedup vs baseline: 1.3786x; 1.0770x over previous
#include <cuda_runtime.h>
#include <cuda_fp16.h>
#include <cstdint>

#define BB 8
#define TT 512
#define SS 512
#define HH 128

// scratch (allocation-free rule: __device__ globals)
__device__ uint32_t g_WS2[BB*TT/2*HH];   // half2: (WS[t_even], WS[t_odd]) per h
__device__ uint32_t g_WH2[BB*SS*HH];     // half2: (WH, WH) duplicated
__device__ uint32_t g_V2 [HH];           // half2: (v, v) duplicated
__device__ float    g_SC [BB*TT*SS];     // raw masked scores (8 MB, L2-resident)
__device__ float    g_CT [BB*TT*HH];

__device__ __forceinline__ uint32_t tanh2_u(uint32_t a){
    uint32_t r; asm("tanh.approx.f16x2 %0, %1;" : "=r"(r) : "r"(a)); return r;
}
__device__ __forceinline__ void cp16(uint32_t smem_dst, const void* gsrc){
    asm volatile("cp.async.ca.shared.global [%0], [%1], 16;" :: "r"(smem_dst), "l"(gsrc));
}
#define CP_COMMIT() asm volatile("cp.async.commit_group;")
template<int N> __device__ __forceinline__ void cp_wait(){
    asm volatile("cp.async.wait_group %0;" :: "n"(N));
}

// ---------------------------------------------------------------------------
// K0: pack v into dup-half2
// ---------------------------------------------------------------------------
__global__ void k_packv(const float* __restrict__ vvec){
    int i = threadIdx.x;
    __half2 d = __half2half2(__float2half_rn(vvec[i]));
    g_V2[i] = *(uint32_t*)&d;
}

// ---------------------------------------------------------------------------
// K1: projections. grid (128, 2): y=0 -> WS(query,W_s) -> g_WS2 (t-paired h2),
//                                 y=1 -> WH(enc,W_h)   -> g_WH2 (dup h2).
// ---------------------------------------------------------------------------
__global__ __launch_bounds__(256) void k_proj(
    const float* __restrict__ q, const float* __restrict__ enc,
    const float* __restrict__ Ws, const float* __restrict__ Wh)
{
    extern __shared__ float sm[];
    float* insm = sm;            // 32 x 128
    float* Wsm  = sm + 32*128;   // 128 cols x 36

    const float* in; const float* W;
    if (blockIdx.y == 0) { in = q;   W = Ws; }
    else                 { in = enc; W = Wh; }
    int tid = threadIdx.x;
    int i0 = blockIdx.x * 32;

    {
        const float4* inv = (const float4*)(in + i0*128);
        float4* insv = (float4*)insm;
        #pragma unroll
        for (int k = 0; k < 4; k++) insv[tid + 256*k] = inv[tid + 256*k];
    }

    int cg = tid & 31;
    int rg = tid >> 5;
    float acc[4][4];
    #pragma unroll
    for (int r = 0; r < 4; r++)
        #pragma unroll
        for (int j = 0; j < 4; j++) acc[r][j] = 0.f;

    #pragma unroll 1
    for (int hc = 0; hc < 4; hc++) {
        __syncthreads();
        #pragma unroll
        for (int k = 0; k < 4; k++) {
            int idx = tid + 256*k;
            int col = idx >> 3, kk = idx & 7;
            float4 w = *(const float4*)(W + col*128 + hc*32 + kk*4);
            *(float4*)(Wsm + col*36 + kk*4) = w;
        }
        __syncthreads();
        #pragma unroll
        for (int k8 = 0; k8 < 8; k8++) {
            float4 cv[4];
            #pragma unroll
            for (int j = 0; j < 4; j++)
                cv[j] = *(const float4*)(Wsm + (cg + 32*j)*36 + k8*4);
            float4 rv[4];
            #pragma unroll
            for (int r = 0; r < 4; r++)
                rv[r] = *(const float4*)(insm + (rg*4 + r)*128 + hc*32 + k8*4);
            #pragma unroll
            for (int r = 0; r < 4; r++)
                #pragma unroll
                for (int j = 0; j < 4; j++) {
                    acc[r][j] += rv[r].x*cv[j].x;
                    acc[r][j] += rv[r].y*cv[j].y;
                    acc[r][j] += rv[r].z*cv[j].z;
                    acc[r][j] += rv[r].w*cv[j].w;
                }
        }
    }
    if (blockIdx.y == 0) {
        #pragma unroll
        for (int r = 0; r < 4; r += 2)
            #pragma unroll
            for (int j = 0; j < 4; j++) {
                __half2 p = __floats2half2_rn(acc[r][j], acc[r+1][j]);  // x=even t
                int pair = (i0 + rg*4 + r) >> 1;
                g_WS2[pair*128 + cg + 32*j] = *(uint32_t*)&p;
            }
    } else {
        #pragma unroll
        for (int r = 0; r < 4; r++)
            #pragma unroll
            for (int j = 0; j < 4; j++) {
                __half2 d = __half2half2(__float2half_rn(acc[r][j]));
                g_WH2[(i0 + rg*4 + r)*128 + cg + 32*j] = *(uint32_t*)&d;
            }
    }
}

// ---------------------------------------------------------------------------
// K2: scores only. grid 2048 = (b, t-tile of 16, s-chunk of 64).
// Early-exit (write zeros) when whole s-chunk masked.
// ---------------------------------------------------------------------------
__global__ __launch_bounds__(256) void k_scores(
    const int* __restrict__ lens)
{
    __shared__ uint32_t s_wh[64*132];   // transposed s-chunk, pad 132
    __shared__ uint32_t s_ws[8*128];    // 8 t-pairs x 128 h
    __shared__ uint32_t s_v [128];      // dup half2 of v

    int bx = blockIdx.x;
    int b  = bx >> 8;
    int tt = (bx >> 3) & 31;
    int sc = bx & 7;
    int t0 = tt*16, s0 = sc*64;
    int tid = threadIdx.x;
    int len = __ldg(&lens[b]);

    if (s0 >= len) {   // fully masked: write zeros (reference quirk)
        int r = tid >> 4, c4 = tid & 15;
        *(float4*)(g_SC + (b*TT + t0 + r)*SS + s0 + c4*4) = make_float4(0.f,0.f,0.f,0.f);
        return;
    }

    uint32_t smbase = (uint32_t)__cvta_generic_to_shared(s_wh);
    {   // stage WH chunk (transposed, cp.async)
        const uint32_t* src = g_WH2 + (b*SS + s0)*128;
        #pragma unroll
        for (int k = 0; k < 8; k++) {
            int idx = tid + 256*k;            // 2048 x 16B
            int ss = idx >> 5, kk = idx & 31;
            cp16(smbase + (ss*132 + kk*4)*4, src + ss*128 + kk*4);
        }
        CP_COMMIT();
    }
    {   // stage ws pairs + v
        const uint32_t* wsrc = g_WS2 + (b*(TT/2) + t0/2)*128;
        #pragma unroll
        for (int k = 0; k < 4; k++) s_ws[tid + 256*k] = wsrc[tid + 256*k];
        if (tid < 128) s_v[tid] = g_V2[tid];
    }
    cp_wait<0>();
    __syncthreads();

    int warp = tid >> 5, lane = tid & 31;
    int tq = warp >> 1, sh = warp & 1;
    int s  = sh*32 + lane;
    const uint32_t* wsA = s_ws + (tq*2 + 0)*128;   // (t=4tq+0, 4tq+1)
    const uint32_t* wsB = s_ws + (tq*2 + 1)*128;   // (t=4tq+2, 4tq+3)
    const uint32_t* whrow = s_wh + s*132;

    float a0 = 0.f, a1 = 0.f, a2 = 0.f, a3 = 0.f;
    #pragma unroll
    for (int hb = 0; hb < 128; hb += 8) {      // flush f16 accumulators every 8 h
        __half2 accA = __float2half2_rn(0.f);
        __half2 accB = __float2half2_rn(0.f);
        #pragma unroll
        for (int g = 0; g < 8; g += 4) {
            uint4 wh4 = *(const uint4*)(whrow + hb + g);
            uint4 wA4 = *(const uint4*)(wsA + hb + g);
            uint4 wB4 = *(const uint4*)(wsB + hb + g);
            uint4 vv4 = *(const uint4*)(s_v + hb + g);
            #define STEP(WH, WA, WB, VV)                                     \
            {                                                                \
                __half2 hw = *(__half2*)&(WH);                               \
                __half2 aA = __hadd2(hw, *(__half2*)&(WA));                  \
                __half2 aB = __hadd2(hw, *(__half2*)&(WB));                  \
                uint32_t tA = tanh2_u(*(uint32_t*)&aA);                      \
                uint32_t tB = tanh2_u(*(uint32_t*)&aB);                      \
                __half2 v2 = *(__half2*)&(VV);                               \
                accA = __hfma2(v2, *(__half2*)&tA, accA);                    \
                accB = __hfma2(v2, *(__half2*)&tB, accB);                    \
            }
            STEP(wh4.x, wA4.x, wB4.x, vv4.x)
            STEP(wh4.y, wA4.y, wB4.y, vv4.y)
            STEP(wh4.z, wA4.z, wB4.z, vv4.z)
            STEP(wh4.w, wA4.w, wB4.w, vv4.w)
            #undef STEP
        }
        float2 fA = __half22float2(accA);
        float2 fB = __half22float2(accB);
        a0 += fA.x; a1 += fA.y;
        a2 += fB.x; a3 += fB.y;
    }
    int sg = s0 + s;
    float m = (sg < len) ? 1.f : 0.f;          // reference quirk: zero, not -inf
    g_SC[(b*TT + t0 + tq*4 + 0)*SS + sg] = a0 * m;
    g_SC[(b*TT + t0 + tq*4 + 1)*SS + sg] = a1 * m;
    g_SC[(b*TT + t0 + tq*4 + 2)*SS + sg] = a2 * m;
    g_SC[(b*TT + t0 + tq*4 + 3)*SS + sg] = a3 * m;
}

// ---------------------------------------------------------------------------
// K3: softmax + ct. grid 512 = (b, t-tile of 8), 256 threads.
// softmax: 1 warp per t-row. ct: warp = 64-s slice x all 8 t, lanes = 4h.
// Partials reduced through (aliased) 32KB smem buffer.
// ---------------------------------------------------------------------------
__global__ __launch_bounds__(256) void k_smct(
    const float* __restrict__ enc)
{
    __shared__ float buf[8*8*128];   // 32KB; [0:4096) = scores (8x512) in ph1/2
    __shared__ float invsum[8];
    float* scores = buf;

    int tid = threadIdx.x;
    int b  = blockIdx.x >> 6;
    int t0 = (blockIdx.x & 63) * 8;
    int warp = tid >> 5, lane = tid & 31;

    {   // stage scores (cp.async, 16 KB, coalesced)
        uint32_t smbase = (uint32_t)__cvta_generic_to_shared(buf);
        const float* src = g_SC + (b*TT + t0)*SS;
        #pragma unroll
        for (int k = 0; k < 4; k++) {
            int idx = tid + 256*k;            // 1024 x 16B
            cp16(smbase + idx*16, src + idx*4);
        }
        CP_COMMIT();
        cp_wait<0>();
        __syncthreads();
    }

    // ---- softmax over full 512 (zeros included); 1 warp per row ----
    {
        int t = warp;
        float* row = scores + t*512;
        float loc[16];
        float mx = -1e30f;
        #pragma unroll
        for (int k = 0; k < 16; k++) { loc[k] = row[lane + 32*k]; mx = fmaxf(mx, loc[k]); }
        #pragma unroll
        for (int o = 16; o > 0; o >>= 1) mx = fmaxf(mx, __shfl_xor_sync(0xffffffffu, mx, o));
        float sum = 0.f;
        #pragma unroll
        for (int k = 0; k < 16; k++) {
            float p = __expf(loc[k] - mx);
            row[lane + 32*k] = p;
            sum += p;
        }
        #pragma unroll
        for (int o = 16; o > 0; o >>= 1) sum += __shfl_xor_sync(0xffffffffu, sum, o);
        if (lane == 0) invsum[t] = 1.f / sum;
    }
    __syncthreads();

    // ---- ct partials: warp w covers s in [w*64, w*64+64), all 8 t ----
    int h0 = lane * 4;
    int sbase = warp * 64;
    float4 acc[8];
    #pragma unroll
    for (int t = 0; t < 8; t++) acc[t] = make_float4(0.f,0.f,0.f,0.f);

    const float* eb = enc + (b*SS)*128;
    #pragma unroll 2
    for (int s4 = 0; s4 < 16; s4++) {
        const float* ps = scores + sbase + s4*4;
        float4 p[8];
        #pragma unroll
        for (int t = 0; t < 8; t++) p[t] = *(const float4*)(ps + t*512);  // uniform
        float4 e0 = __ldg((const float4*)(eb + (sbase + s4*4 + 0)*128 + h0));
        float4 e1 = __ldg((const float4*)(eb + (sbase + s4*4 + 1)*128 + h0));
        float4 e2 = __ldg((const float4*)(eb + (sbase + s4*4 + 2)*128 + h0));
        float4 e3 = __ldg((const float4*)(eb + (sbase + s4*4 + 3)*128 + h0));
        #pragma unroll
        for (int t = 0; t < 8; t++) {
            acc[t].x += p[t].x*e0.x + p[t].y*e1.x + p[t].z*e2.x + p[t].w*e3.x;
            acc[t].y += p[t].x*e0.y + p[t].y*e1.y + p[t].z*e2.y + p[t].w*e3.y;
            acc[t].z += p[t].x*e0.z + p[t].y*e1.z + p[t].z*e2.z + p[t].w*e3.z;
            acc[t].w += p[t].x*e0.w + p[t].y*e1.w + p[t].z*e2.w + p[t].w*e3.w;
        }
    }
    __syncthreads();                 // all score reads done; buf reusable
    {   // write partials: [warp][t][h]
        float* dst = buf + (warp*8)*128;
        #pragma unroll
        for (int t = 0; t < 8; t++)
            *(float4*)(dst + t*128 + h0) = acc[t];
    }
    __syncthreads();
    {   // reduce 8 slices; thread = (t = tid>>5, h-quad = lane)
        int t = warp;
        float4 r = make_float4(0.f,0.f,0.f,0.f);
        #pragma unroll
        for (int sl = 0; sl < 8; sl++) {
            float4 v = *(const float4*)(buf + (sl*8 + t)*128 + h0);
            r.x += v.x; r.y += v.y; r.z += v.z; r.w += v.w;
        }
        float iv = invsum[t];
        r.x *= iv; r.y *= iv; r.z *= iv; r.w *= iv;
        *(float4*)(g_CT + (b*TT + t0 + t)*128 + h0) = r;
    }
}

// ---------------------------------------------------------------------------
// K4: out = tanh(W_out . concat + b). grid 256; 128 threads; thread = 4t x 4o.
// ---------------------------------------------------------------------------
__global__ __launch_bounds__(128, 2) void k_out(
    const float* __restrict__ q, const float* __restrict__ Wout,
    const float* __restrict__ bias, float* __restrict__ out)
{
    extern __shared__ float sm[];
    float* concat = sm;               // 16 x 256
    float* Wsm    = concat + 16*256;  // 128 x 132
    float* bsm    = Wsm + 128*132;    // 128

    int tid = threadIdx.x;
    int b  = blockIdx.x >> 5;
    int t0 = (blockIdx.x & 31) * 16;

    {
        #pragma unroll
        for (int k = 0; k < 8; k++) {
            int idx = tid + 128*k;          // 1024 float4
            int t = idx >> 6, c4 = idx & 63;
            float4 v;
            if (c4 < 32) v = *(const float4*)(g_CT + (b*TT + t0 + t)*128 + c4*4);
            else         v = *(const float4*)(q    + (b*TT + t0 + t)*128 + (c4-32)*4);
            *(float4*)(concat + t*256 + c4*4) = v;
        }
    }
    bsm[tid] = bias[tid];

    int og = tid & 31;          // o = og + 32*j
    int tg = tid >> 5;          // 4 t-groups of 4 t
    float acc[4][4];
    #pragma unroll
    for (int t = 0; t < 4; t++)
        #pragma unroll
        for (int j = 0; j < 4; j++) acc[t][j] = 0.f;

    for (int c0 = 0; c0 < 256; c0 += 128) {
        __syncthreads();
        #pragma unroll
        for (int k = 0; k < 32; k++) {        // 4096 float4
            int idx = tid + 128*k;
            int o = idx >> 5, kk = idx & 31;
            float4 w = *(const float4*)(Wout + o*256 + c0 + kk*4);
            *(float4*)(Wsm + o*132 + kk*4) = w;
        }
        __syncthreads();
        #pragma unroll 4
        for (int cl = 0; cl < 128; cl += 4) {
            float4 w[4];
            #pragma unroll
            for (int j = 0; j < 4; j++)
                w[j] = *(const float4*)(Wsm + (og + 32*j)*132 + cl);
            #pragma unroll
            for (int t = 0; t < 4; t++) {
                float4 cc = *(const float4*)(concat + (tg*4 + t)*256 + c0 + cl);
                #pragma unroll
                for (int j = 0; j < 4; j++)
                    acc[t][j] += w[j].x*cc.x + w[j].y*cc.y + w[j].z*cc.z + w[j].w*cc.w;
            }
        }
    }
    #pragma unroll
    for (int t = 0; t < 4; t++) {
        int tt = t0 + tg*4 + t;
        #pragma unroll
        for (int j = 0; j < 4; j++)
            out[(b*TT + tt)*128 + og + 32*j] = tanhf(acc[t][j] + bsm[og + 32*j]);
    }
}

// ---------------------------------------------------------------------------
extern "C" void kernel_launch(void* const* d_in, const int* in_sizes, int n_in,
                              void* d_out, int out_size)
{
    (void)in_sizes; (void)n_in; (void)out_size;
    const float* q    = (const float*)d_in[0];
    const float* enc  = (const float*)d_in[1];
    const int*   lens = (const int*)  d_in[2];
    const float* Wh   = (const float*)d_in[3];
    const float* Ws   = (const float*)d_in[4];
    const float* v    = (const float*)d_in[5];
    const float* Wout = (const float*)d_in[6];
    const float* bias = (const float*)d_in[7];
    float* out = (float*)d_out;

    int sm1 = (32*128 + 128*36) * 4;            // 34816 B
    int sm4 = (16*256 + 128*132 + 128) * 4;     // 84480 B
    cudaFuncSetAttribute(k_proj, cudaFuncAttributeMaxDynamicSharedMemorySize, sm1);
    cudaFuncSetAttribute(k_out,  cudaFuncAttributeMaxDynamicSharedMemorySize, sm4);

    dim3 g1(128, 2);
    k_packv<<<1, 128>>>(v);
    k_proj<<<g1, 256, sm1>>>(q, enc, Ws, Wh);
    k_scores<<<2048, 256>>>(lens);
    k_smct<<<512, 256>>>(enc);
    k_out<<<256, 128, sm4>>>(q, Wout, bias, out);
}

// round 10
// speedup vs baseline: 1.4343x; 1.0404x over previous
#include <cuda_runtime.h>
#include <cuda_fp16.h>
#include <cstdint>

#define BB 8
#define TT 512
#define SS 512
#define HH 128

// scratch (allocation-free rule: __device__ globals)
__device__ uint32_t g_WS2[BB*TT/2*HH];   // half2: (WS[t_even], WS[t_odd]) per h
__device__ uint32_t g_WH2[BB*SS*HH];     // half2: (WH, WH) duplicated
__device__ uint32_t g_V2 [HH];           // half2: (v, v) duplicated
__device__ float    g_SC [BB*TT*SS];     // raw masked scores (8 MB, L2-resident)
__device__ float    g_CT [BB*TT*HH];

__device__ __forceinline__ uint32_t tanh2_u(uint32_t a){
    uint32_t r; asm("tanh.approx.f16x2 %0, %1;" : "=r"(r) : "r"(a)); return r;
}
__device__ __forceinline__ void cp16(uint32_t smem_dst, const void* gsrc){
    asm volatile("cp.async.ca.shared.global [%0], [%1], 16;" :: "r"(smem_dst), "l"(gsrc));
}
#define CP_COMMIT() asm volatile("cp.async.commit_group;")
template<int N> __device__ __forceinline__ void cp_wait(){
    asm volatile("cp.async.wait_group %0;" :: "n"(N));
}

// ---------------------------------------------------------------------------
// K1: projections. grid (128, 2): y=0 -> WS(query,W_s) -> g_WS2 (t-paired h2),
//                                 y=1 -> WH(enc,W_h)   -> g_WH2 (dup h2).
// Block (0,0) also packs v into g_V2 (folded k_packv).
// ---------------------------------------------------------------------------
__global__ __launch_bounds__(256) void k_proj(
    const float* __restrict__ q, const float* __restrict__ enc,
    const float* __restrict__ Ws, const float* __restrict__ Wh,
    const float* __restrict__ vvec)
{
    extern __shared__ float sm[];
    float* insm = sm;            // 32 x 128
    float* Wsm  = sm + 32*128;   // 128 cols x 36

    const float* in; const float* W;
    if (blockIdx.y == 0) { in = q;   W = Ws; }
    else                 { in = enc; W = Wh; }
    int tid = threadIdx.x;
    int i0 = blockIdx.x * 32;

    if (blockIdx.x == 0 && blockIdx.y == 0 && tid < 128) {
        __half2 d = __half2half2(__float2half_rn(vvec[tid]));
        g_V2[tid] = *(uint32_t*)&d;
    }

    {
        const float4* inv = (const float4*)(in + i0*128);
        float4* insv = (float4*)insm;
        #pragma unroll
        for (int k = 0; k < 4; k++) insv[tid + 256*k] = inv[tid + 256*k];
    }

    int cg = tid & 31;
    int rg = tid >> 5;
    float acc[4][4];
    #pragma unroll
    for (int r = 0; r < 4; r++)
        #pragma unroll
        for (int j = 0; j < 4; j++) acc[r][j] = 0.f;

    #pragma unroll 1
    for (int hc = 0; hc < 4; hc++) {
        __syncthreads();
        #pragma unroll
        for (int k = 0; k < 4; k++) {
            int idx = tid + 256*k;
            int col = idx >> 3, kk = idx & 7;
            float4 w = *(const float4*)(W + col*128 + hc*32 + kk*4);
            *(float4*)(Wsm + col*36 + kk*4) = w;
        }
        __syncthreads();
        #pragma unroll
        for (int k8 = 0; k8 < 8; k8++) {
            float4 cv[4];
            #pragma unroll
            for (int j = 0; j < 4; j++)
                cv[j] = *(const float4*)(Wsm + (cg + 32*j)*36 + k8*4);
            float4 rv[4];
            #pragma unroll
            for (int r = 0; r < 4; r++)
                rv[r] = *(const float4*)(insm + (rg*4 + r)*128 + hc*32 + k8*4);
            #pragma unroll
            for (int r = 0; r < 4; r++)
                #pragma unroll
                for (int j = 0; j < 4; j++) {
                    acc[r][j] += rv[r].x*cv[j].x;
                    acc[r][j] += rv[r].y*cv[j].y;
                    acc[r][j] += rv[r].z*cv[j].z;
                    acc[r][j] += rv[r].w*cv[j].w;
                }
        }
    }
    if (blockIdx.y == 0) {
        #pragma unroll
        for (int r = 0; r < 4; r += 2)
            #pragma unroll
            for (int j = 0; j < 4; j++) {
                __half2 p = __floats2half2_rn(acc[r][j], acc[r+1][j]);  // x=even t
                int pair = (i0 + rg*4 + r) >> 1;
                g_WS2[pair*128 + cg + 32*j] = *(uint32_t*)&p;
            }
    } else {
        #pragma unroll
        for (int r = 0; r < 4; r++)
            #pragma unroll
            for (int j = 0; j < 4; j++) {
                __half2 d = __half2half2(__float2half_rn(acc[r][j]));
                g_WH2[(i0 + rg*4 + r)*128 + cg + 32*j] = *(uint32_t*)&d;
            }
    }
}

// ---------------------------------------------------------------------------
// K2: scores only. grid 2048 = (b, t-tile of 16, s-chunk of 64).
// Early-exit (write zeros) when whole s-chunk masked.
// ---------------------------------------------------------------------------
__global__ __launch_bounds__(256) void k_scores(
    const int* __restrict__ lens)
{
    __shared__ uint32_t s_wh[64*132];   // transposed s-chunk, pad 132
    __shared__ uint32_t s_ws[8*128];    // 8 t-pairs x 128 h
    __shared__ uint32_t s_v [128];      // dup half2 of v

    int bx = blockIdx.x;
    int b  = bx >> 8;
    int tt = (bx >> 3) & 31;
    int sc = bx & 7;
    int t0 = tt*16, s0 = sc*64;
    int tid = threadIdx.x;
    int len = __ldg(&lens[b]);

    if (s0 >= len) {   // fully masked: write zeros (reference quirk)
        int r = tid >> 4, c4 = tid & 15;
        *(float4*)(g_SC + (b*TT + t0 + r)*SS + s0 + c4*4) = make_float4(0.f,0.f,0.f,0.f);
        return;
    }

    uint32_t smbase = (uint32_t)__cvta_generic_to_shared(s_wh);
    {   // stage WH chunk (transposed, cp.async)
        const uint32_t* src = g_WH2 + (b*SS + s0)*128;
        #pragma unroll
        for (int k = 0; k < 8; k++) {
            int idx = tid + 256*k;            // 2048 x 16B
            int ss = idx >> 5, kk = idx & 31;
            cp16(smbase + (ss*132 + kk*4)*4, src + ss*128 + kk*4);
        }
        CP_COMMIT();
    }
    {   // stage ws pairs + v
        const uint32_t* wsrc = g_WS2 + (b*(TT/2) + t0/2)*128;
        #pragma unroll
        for (int k = 0; k < 4; k++) s_ws[tid + 256*k] = wsrc[tid + 256*k];
        if (tid < 128) s_v[tid] = g_V2[tid];
    }
    cp_wait<0>();
    __syncthreads();

    int warp = tid >> 5, lane = tid & 31;
    int tq = warp >> 1, sh = warp & 1;
    int s  = sh*32 + lane;
    const uint32_t* wsA = s_ws + (tq*2 + 0)*128;   // (t=4tq+0, 4tq+1)
    const uint32_t* wsB = s_ws + (tq*2 + 1)*128;   // (t=4tq+2, 4tq+3)
    const uint32_t* whrow = s_wh + s*132;

    float a0 = 0.f, a1 = 0.f, a2 = 0.f, a3 = 0.f;
    #pragma unroll
    for (int hb = 0; hb < 128; hb += 8) {      // flush f16 accumulators every 8 h
        __half2 accA = __float2half2_rn(0.f);
        __half2 accB = __float2half2_rn(0.f);
        #pragma unroll
        for (int g = 0; g < 8; g += 4) {
            uint4 wh4 = *(const uint4*)(whrow + hb + g);
            uint4 wA4 = *(const uint4*)(wsA + hb + g);
            uint4 wB4 = *(const uint4*)(wsB + hb + g);
            uint4 vv4 = *(const uint4*)(s_v + hb + g);
            #define STEP(WH, WA, WB, VV)                                     \
            {                                                                \
                __half2 hw = *(__half2*)&(WH);                               \
                __half2 aA = __hadd2(hw, *(__half2*)&(WA));                  \
                __half2 aB = __hadd2(hw, *(__half2*)&(WB));                  \
                uint32_t tA = tanh2_u(*(uint32_t*)&aA);                      \
                uint32_t tB = tanh2_u(*(uint32_t*)&aB);                      \
                __half2 v2 = *(__half2*)&(VV);                               \
                accA = __hfma2(v2, *(__half2*)&tA, accA);                    \
                accB = __hfma2(v2, *(__half2*)&tB, accB);                    \
            }
            STEP(wh4.x, wA4.x, wB4.x, vv4.x)
            STEP(wh4.y, wA4.y, wB4.y, vv4.y)
            STEP(wh4.z, wA4.z, wB4.z, vv4.z)
            STEP(wh4.w, wA4.w, wB4.w, vv4.w)
            #undef STEP
        }
        float2 fA = __half22float2(accA);
        float2 fB = __half22float2(accB);
        a0 += fA.x; a1 += fA.y;
        a2 += fB.x; a3 += fB.y;
    }
    int sg = s0 + s;
    float m = (sg < len) ? 1.f : 0.f;          // reference quirk: zero, not -inf
    g_SC[(b*TT + t0 + tq*4 + 0)*SS + sg] = a0 * m;
    g_SC[(b*TT + t0 + tq*4 + 1)*SS + sg] = a1 * m;
    g_SC[(b*TT + t0 + tq*4 + 2)*SS + sg] = a2 * m;
    g_SC[(b*TT + t0 + tq*4 + 3)*SS + sg] = a3 * m;
}

// ---------------------------------------------------------------------------
// K3: softmax + ct. grid 512 = (b, t-tile of 8), 256 threads, 4 CTAs/SM.
// softmax: 1 warp per t-row. ct: warp = 64-s slice x all 8 t, lanes = 4h.
// p loaded per-t (keeps regs < 64 for occupancy 4).
// ---------------------------------------------------------------------------
__global__ __launch_bounds__(256, 4) void k_smct(
    const float* __restrict__ enc)
{
    __shared__ float buf[8*8*128];   // 32KB; [0:4096) = scores (8x512) in ph1/2
    __shared__ float invsum[8];
    float* scores = buf;

    int tid = threadIdx.x;
    int b  = blockIdx.x >> 6;
    int t0 = (blockIdx.x & 63) * 8;
    int warp = tid >> 5, lane = tid & 31;

    {   // stage scores (cp.async, 16 KB, coalesced)
        uint32_t smbase = (uint32_t)__cvta_generic_to_shared(buf);
        const float* src = g_SC + (b*TT + t0)*SS;
        #pragma unroll
        for (int k = 0; k < 4; k++) {
            int idx = tid + 256*k;            // 1024 x 16B
            cp16(smbase + idx*16, src + idx*4);
        }
        CP_COMMIT();
        cp_wait<0>();
        __syncthreads();
    }

    // ---- softmax over full 512 (zeros included); 1 warp per row ----
    {
        int t = warp;
        float* row = scores + t*512;
        float loc[16];
        float mx = -1e30f;
        #pragma unroll
        for (int k = 0; k < 16; k++) { loc[k] = row[lane + 32*k]; mx = fmaxf(mx, loc[k]); }
        #pragma unroll
        for (int o = 16; o > 0; o >>= 1) mx = fmaxf(mx, __shfl_xor_sync(0xffffffffu, mx, o));
        float sum = 0.f;
        #pragma unroll
        for (int k = 0; k < 16; k++) {
            float p = __expf(loc[k] - mx);
            row[lane + 32*k] = p;
            sum += p;
        }
        #pragma unroll
        for (int o = 16; o > 0; o >>= 1) sum += __shfl_xor_sync(0xffffffffu, sum, o);
        if (lane == 0) invsum[t] = 1.f / sum;
    }
    __syncthreads();

    // ---- ct partials: warp w covers s in [w*64, w*64+64), all 8 t ----
    int h0 = lane * 4;
    int sbase = warp * 64;
    float4 acc[8];
    #pragma unroll
    for (int t = 0; t < 8; t++) acc[t] = make_float4(0.f,0.f,0.f,0.f);

    const float* eb = enc + (b*SS)*128;
    #pragma unroll 2
    for (int s4 = 0; s4 < 16; s4++) {
        float4 e0 = __ldg((const float4*)(eb + (sbase + s4*4 + 0)*128 + h0));
        float4 e1 = __ldg((const float4*)(eb + (sbase + s4*4 + 1)*128 + h0));
        float4 e2 = __ldg((const float4*)(eb + (sbase + s4*4 + 2)*128 + h0));
        float4 e3 = __ldg((const float4*)(eb + (sbase + s4*4 + 3)*128 + h0));
        const float* ps = scores + sbase + s4*4;
        #pragma unroll
        for (int t = 0; t < 8; t++) {
            float4 p = *(const float4*)(ps + t*512);   // uniform LDS.128
            acc[t].x += p.x*e0.x + p.y*e1.x + p.z*e2.x + p.w*e3.x;
            acc[t].y += p.x*e0.y + p.y*e1.y + p.z*e2.y + p.w*e3.y;
            acc[t].z += p.x*e0.z + p.y*e1.z + p.z*e2.z + p.w*e3.z;
            acc[t].w += p.x*e0.w + p.y*e1.w + p.z*e2.w + p.w*e3.w;
        }
    }
    __syncthreads();                 // all score reads done; buf reusable
    {   // write partials: [warp][t][h]
        float* dst = buf + (warp*8)*128;
        #pragma unroll
        for (int t = 0; t < 8; t++)
            *(float4*)(dst + t*128 + h0) = acc[t];
    }
    __syncthreads();
    {   // reduce 8 slices; thread = (t = warp, h-quad = lane)
        int t = warp;
        float4 r = make_float4(0.f,0.f,0.f,0.f);
        #pragma unroll
        for (int sl = 0; sl < 8; sl++) {
            float4 v = *(const float4*)(buf + (sl*8 + t)*128 + h0);
            r.x += v.x; r.y += v.y; r.z += v.z; r.w += v.w;
        }
        float iv = invsum[t];
        r.x *= iv; r.y *= iv; r.z *= iv; r.w *= iv;
        *(float4*)(g_CT + (b*TT + t0 + t)*128 + h0) = r;
    }
}

// ---------------------------------------------------------------------------
// K4: out = tanh(W_out . concat + b). grid 256; 128 threads; thread = 4t x 4o.
// ---------------------------------------------------------------------------
__global__ __launch_bounds__(128, 2) void k_out(
    const float* __restrict__ q, const float* __restrict__ Wout,
    const float* __restrict__ bias, float* __restrict__ out)
{
    extern __shared__ float sm[];
    float* concat = sm;               // 16 x 256
    float* Wsm    = concat + 16*256;  // 128 x 132
    float* bsm    = Wsm + 128*132;    // 128

    int tid = threadIdx.x;
    int b  = blockIdx.x >> 5;
    int t0 = (blockIdx.x & 31) * 16;

    {
        #pragma unroll
        for (int k = 0; k < 8; k++) {
            int idx = tid + 128*k;          // 1024 float4
            int t = idx >> 6, c4 = idx & 63;
            float4 v;
            if (c4 < 32) v = *(const float4*)(g_CT + (b*TT + t0 + t)*128 + c4*4);
            else         v = *(const float4*)(q    + (b*TT + t0 + t)*128 + (c4-32)*4);
            *(float4*)(concat + t*256 + c4*4) = v;
        }
    }
    bsm[tid] = bias[tid];

    int og = tid & 31;          // o = og + 32*j
    int tg = tid >> 5;          // 4 t-groups of 4 t
    float acc[4][4];
    #pragma unroll
    for (int t = 0; t < 4; t++)
        #pragma unroll
        for (int j = 0; j < 4; j++) acc[t][j] = 0.f;

    for (int c0 = 0; c0 < 256; c0 += 128) {
        __syncthreads();
        #pragma unroll
        for (int k = 0; k < 32; k++) {        // 4096 float4
            int idx = tid + 128*k;
            int o = idx >> 5, kk = idx & 31;
            float4 w = *(const float4*)(Wout + o*256 + c0 + kk*4);
            *(float4*)(Wsm + o*132 + kk*4) = w;
        }
        __syncthreads();
        #pragma unroll 4
        for (int cl = 0; cl < 128; cl += 4) {
            float4 w[4];
            #pragma unroll
            for (int j = 0; j < 4; j++)
                w[j] = *(const float4*)(Wsm + (og + 32*j)*132 + cl);
            #pragma unroll
            for (int t = 0; t < 4; t++) {
                float4 cc = *(const float4*)(concat + (tg*4 + t)*256 + c0 + cl);
                #pragma unroll
                for (int j = 0; j < 4; j++)
                    acc[t][j] += w[j].x*cc.x + w[j].y*cc.y + w[j].z*cc.z + w[j].w*cc.w;
            }
        }
    }
    #pragma unroll
    for (int t = 0; t < 4; t++) {
        int tt = t0 + tg*4 + t;
        #pragma unroll
        for (int j = 0; j < 4; j++)
            out[(b*TT + tt)*128 + og + 32*j] = tanhf(acc[t][j] + bsm[og + 32*j]);
    }
}

// ---------------------------------------------------------------------------
extern "C" void kernel_launch(void* const* d_in, const int* in_sizes, int n_in,
                              void* d_out, int out_size)
{
    (void)in_sizes; (void)n_in; (void)out_size;
    const float* q    = (const float*)d_in[0];
    const float* enc  = (const float*)d_in[1];
    const int*   lens = (const int*)  d_in[2];
    const float* Wh   = (const float*)d_in[3];
    const float* Ws   = (const float*)d_in[4];
    const float* v    = (const float*)d_in[5];
    const float* Wout = (const float*)d_in[6];
    const float* bias = (const float*)d_in[7];
    float* out = (float*)d_out;

    int sm1 = (32*128 + 128*36) * 4;            // 34816 B
    int sm4 = (16*256 + 128*132 + 128) * 4;     // 84480 B
    cudaFuncSetAttribute(k_proj, cudaFuncAttributeMaxDynamicSharedMemorySize, sm1);
    cudaFuncSetAttribute(k_out,  cudaFuncAttributeMaxDynamicSharedMemorySize, sm4);

    dim3 g1(128, 2);
    k_proj<<<g1, 256, sm1>>>(q, enc, Ws, Wh, v);
    k_scores<<<2048, 256>>>(lens);
    k_smct<<<512, 256>>>(enc);
    k_out<<<256, 128, sm4>>>(q, Wout, bias, out);
}